// round 11
// baseline (speedup 1.0000x reference)
#include <cuda_runtime.h>
#include <float.h>

// WOS: O(D^2/2) symmetric rank-by-counting, THREE-way tiling (18 each).
// Only the live tile's (mx, acc, w) is register-resident (~54 array regs);
// parked tiles stage acc ONLY in per-thread smem (stride 37, conflict-free),
// mx is recomputed from ptile+msk on demand. Targets 5 blocks/SM (20 warps)
// with zero forced spills.

#define NCH   16
#define DTOT  54
#define DHALF 27
#define TS    18          // tile size (3 tiles)
#define TOL   1e-6f
#define PX    8           // pixels per block
#define ASTR  37          // parked-acc stride per thread (odd: conflict-free)

// i < j by construction: ties (>=) put i before j (stable argsort).
// Winner's weight charged to the loser's accumulator (s may alias acc_i).
__device__ __forceinline__ void pair_update(float& accj, float& acci,
                                            float mi, float mj,
                                            float wi, float wj) {
    asm volatile("{\n\t"
        ".reg .pred p;\n\t"
        "setp.ge.f32 p, %2, %3;\n\t"
        "@p  add.f32 %0, %0, %4;\n\t"
        "@!p add.f32 %1, %1, %5;\n\t"
        "}" : "+f"(accj), "+f"(acci)
            : "f"(mi), "f"(mj), "f"(wi), "f"(wj));
}

__global__ __launch_bounds__(128, 5)
void wos_kernel(const float* __restrict__ x,
                const float* __restrict__ mask,
                const float* __restrict__ weight,
                const float* __restrict__ bias,
                float* __restrict__ out)
{
    __shared__ float msk[NCH * DTOT];        // mask per nc
    __shared__ float wgs[NCH * DTOT];        // gated weights: w>tol ? w : 0
    __shared__ float ptile[3][3][PX + 2];    // halo tile for PX pixels
    __shared__ float accs[128 * ASTR];       // parked acc, tiles 0-1 (36 slots/thread)

    const int tid = threadIdx.x + threadIdx.y * 16;   // x = nc(16), y = pixel(PX)

    for (int e = tid; e < NCH * DTOT; e += 128) {
        msk[e] = mask[e];
        float w = weight[e];
        wgs[e] = (w > TOL) ? w : 0.0f;
    }

    const int n0  = blockIdx.x * PX;         // PX consecutive pixels, same (b,h)
    const int b   = n0 >> 12;
    const int rem = n0 & 4095;
    const int h   = rem >> 6;
    const int w0  = rem & 63;

    for (int e = tid; e < 3 * 3 * (PX + 2); e += 128) {
        int c   = e / (3 * (PX + 2));
        int r   = (e / (PX + 2)) % 3;
        int col = e % (PX + 2);
        int gr  = h - 1 + r;
        int gc  = w0 - 1 + col;
        float v = 0.0f;
        if ((unsigned)gr < 64u && (unsigned)gc < 64u)
            v = x[((b * 3 + c) * 64 + gr) * 64 + gc];
        ptile[c][r][col] = v;
    }
    __syncthreads();

    const int nc = threadIdx.x;
    const int py = threadIdx.y;
    const int n  = n0 + py;
    const int mb = nc * DTOT;
    const int sb = tid * ASTR;               // this thread's parked-acc slice

    // mx(g) recompute: g in 0..53, compile-time g -> folds to LDS+LDS+FADD.
    #define MX_OF(g) ((g) < DHALF \
        ? ptile[(g) / 9][((g) / 3) % 3][py + (g) % 3] + msk[mb + (g)] \
        : msk[mb + (g)] - ptile[((g) - DHALF) / 9][(((g) - DHALF) / 3) % 3][py + ((g) - DHALF) % 3])

    float mxt[TS], acct[TS], wt[TS];

    #pragma unroll
    for (int t = 0; t < 3; t++) {
        // ---- build tile t in registers ----
        #pragma unroll
        for (int d = 0; d < TS; d++) {
            const int g = t * TS + d;
            mxt[d]  = MX_OF(g);
            wt[d]   = wgs[mb + g];
            acct[d] = wt[d];                 // inclusive: starts at own weight
        }

        // ---- in-tile pairs ----
        #pragma unroll
        for (int i = 0; i < TS - 1; i++)
            #pragma unroll
            for (int j = i + 1; j < TS; j++)
                pair_update(acct[j], acct[i], mxt[i], mxt[j], wt[i], wt[j]);

        // ---- cross pairs vs earlier (parked) tiles: global i < j holds ----
        #pragma unroll
        for (int ta = 0; ta < t; ta++) {
            #pragma unroll
            for (int i = 0; i < TS; i++) {
                const int gi = ta * TS + i;
                float mi = MX_OF(gi);        // recompute (2 LDS + FADD)
                float wi = wgs[mb + gi];
                float s  = 0.0f;             // loser-side partial for parked acc
                #pragma unroll
                for (int jj = 0; jj < TS; jj++)
                    pair_update(acct[jj], s, mi, mxt[jj], wi, wt[jj]);
                accs[sb + gi] += s;          // per-thread RMW, no races
            }
        }

        // ---- park tiles 0 and 1 (tile 2 stays in registers) ----
        if (t < 2) {
            #pragma unroll
            for (int d = 0; d < TS; d++)
                accs[sb + t * TS + d] = acct[d];
        }
    }

    // ================= selection epilogue =================
    const float biasv = bias[nc];
    float selMin = FLT_MAX;
    float fbMax  = -FLT_MAX;
    int found = 0, anynz = 0;

    #pragma unroll
    for (int g = 0; g < 2 * TS; g++) {       // parked tiles 0-1
        float wjv = wgs[mb + g];
        if (wjv > 0.0f) {
            anynz = 1;
            float vj = MX_OF(g);
            fbMax = fmaxf(fbMax, vj);
            if (accs[sb + g] <= biasv) { found = 1; selMin = fminf(selMin, vj); }
        }
    }
    #pragma unroll
    for (int d = 0; d < TS; d++) {           // tile 2 from registers
        if (wt[d] > 0.0f) {
            anynz = 1;
            float vj = mxt[d];
            fbMax = fmaxf(fbMax, vj);
            if (acct[d] <= biasv) { found = 1; selMin = fminf(selMin, vj); }
        }
    }

    float res = found ? selMin : (anynz ? fbMax : 0.0f);
    out[n * NCH + nc] = res;                 // flat layout: coalesced per warp

    #undef MX_OF
}

extern "C" void kernel_launch(void* const* d_in, const int* in_sizes, int n_in,
                              void* d_out, int out_size) {
    const float* x      = (const float*)d_in[0];
    const float* mask   = (const float*)d_in[1];
    const float* weight = (const float*)d_in[2];
    const float* bias   = (const float*)d_in[3];
    float* out = (float*)d_out;

    // 32768 pixels / 8 per block = 4096 blocks; block = 16 nc x 8 pixels
    wos_kernel<<<4096, dim3(16, PX)>>>(x, mask, weight, bias, out);
}

// round 15
// speedup vs baseline: 1.1187x; 1.1187x over previous
#include <cuda_runtime.h>
#include <float.h>

// WOS: O(D^2/2) symmetric rank-by-counting, two-phase 27-tiling (R10 base).
// Pair updates batched 6-at-a-time in one asm block: 6 FSETPs up front
// (6 predicate regs), then 12 guarded FADDs. This hides the 13-cyc
// pred-as-guard latency that single-pair asm blocks exposed (~31% dead
// issue slots across R6-R11 regardless of occupancy).

#define NCH   16
#define DTOT  54
#define DHALF 27
#define TOL   1e-6f
#define PX    8           // pixels per block

// ---- batched pair updates. i < j by construction; ties (>=) -> i first. ----
// Winner's weight to loser's acc: @q acc_j += wi ; @!q s += wj.
__device__ __forceinline__ void pair6(
    float& a0, float& a1, float& a2, float& a3, float& a4, float& a5,
    float& s0, float& s1, float mi,
    float m0, float m1, float m2, float m3, float m4, float m5,
    float wi,
    float w0, float w1, float w2, float w3, float w4, float w5)
{
    asm volatile("{\n\t"
        ".reg .pred q0,q1,q2,q3,q4,q5;\n\t"
        "setp.ge.f32 q0, %8, %9;\n\t"
        "setp.ge.f32 q1, %8, %10;\n\t"
        "setp.ge.f32 q2, %8, %11;\n\t"
        "setp.ge.f32 q3, %8, %12;\n\t"
        "setp.ge.f32 q4, %8, %13;\n\t"
        "setp.ge.f32 q5, %8, %14;\n\t"
        "@q0 add.f32 %0, %0, %15;\n\t"
        "@q1 add.f32 %1, %1, %15;\n\t"
        "@q2 add.f32 %2, %2, %15;\n\t"
        "@q3 add.f32 %3, %3, %15;\n\t"
        "@q4 add.f32 %4, %4, %15;\n\t"
        "@q5 add.f32 %5, %5, %15;\n\t"
        "@!q0 add.f32 %6, %6, %16;\n\t"
        "@!q1 add.f32 %7, %7, %17;\n\t"
        "@!q2 add.f32 %6, %6, %18;\n\t"
        "@!q3 add.f32 %7, %7, %19;\n\t"
        "@!q4 add.f32 %6, %6, %20;\n\t"
        "@!q5 add.f32 %7, %7, %21;\n\t"
        "}"
        : "+f"(a0), "+f"(a1), "+f"(a2), "+f"(a3), "+f"(a4), "+f"(a5),
          "+f"(s0), "+f"(s1)
        : "f"(mi), "f"(m0), "f"(m1), "f"(m2), "f"(m3), "f"(m4), "f"(m5),
          "f"(wi), "f"(w0), "f"(w1), "f"(w2), "f"(w3), "f"(w4), "f"(w5));
}

__device__ __forceinline__ void pair3(
    float& a0, float& a1, float& a2, float& s0, float mi,
    float m0, float m1, float m2, float wi, float w0, float w1, float w2)
{
    asm volatile("{\n\t"
        ".reg .pred q0,q1,q2;\n\t"
        "setp.ge.f32 q0, %4, %5;\n\t"
        "setp.ge.f32 q1, %4, %6;\n\t"
        "setp.ge.f32 q2, %4, %7;\n\t"
        "@q0 add.f32 %0, %0, %8;\n\t"
        "@q1 add.f32 %1, %1, %8;\n\t"
        "@q2 add.f32 %2, %2, %8;\n\t"
        "@!q0 add.f32 %3, %3, %9;\n\t"
        "@!q1 add.f32 %3, %3, %10;\n\t"
        "@!q2 add.f32 %3, %3, %11;\n\t"
        "}"
        : "+f"(a0), "+f"(a1), "+f"(a2), "+f"(s0)
        : "f"(mi), "f"(m0), "f"(m1), "f"(m2),
          "f"(wi), "f"(w0), "f"(w1), "f"(w2));
}

__device__ __forceinline__ void pair1(float& accj, float& s,
                                      float mi, float mj, float wi, float wj) {
    asm volatile("{\n\t"
        ".reg .pred p;\n\t"
        "setp.ge.f32 p, %2, %3;\n\t"
        "@p  add.f32 %0, %0, %4;\n\t"
        "@!p add.f32 %1, %1, %5;\n\t"
        "}" : "+f"(accj), "+f"(s)
            : "f"(mi), "f"(mj), "f"(wi), "f"(wj));
}

// triangle over a 27-entry register tile: all pairs i<j, batched
__device__ __forceinline__ void triangle27(float (&mxt)[DHALF],
                                           float (&acct)[DHALF],
                                           float (&wt)[DHALF])
{
    #pragma unroll
    for (int i = 0; i < DHALF - 1; i++) {
        float s0 = 0.0f, s1 = 0.0f;
        const int jb  = i + 1;
        const int len = DHALF - jb;          // 26..1
        #pragma unroll
        for (int k = 0; k < len / 6; k++) {
            const int j = jb + k * 6;
            pair6(acct[j], acct[j+1], acct[j+2], acct[j+3], acct[j+4], acct[j+5],
                  s0, s1, mxt[i],
                  mxt[j], mxt[j+1], mxt[j+2], mxt[j+3], mxt[j+4], mxt[j+5],
                  wt[i],
                  wt[j], wt[j+1], wt[j+2], wt[j+3], wt[j+4], wt[j+5]);
        }
        const int rem = len % 6;
        const int jr  = jb + (len / 6) * 6;
        if (rem >= 3)
            pair3(acct[jr], acct[jr+1], acct[jr+2], s0, mxt[i],
                  mxt[jr], mxt[jr+1], mxt[jr+2], wt[i],
                  wt[jr], wt[jr+1], wt[jr+2]);
        const int jr2 = jr + ((rem >= 3) ? 3 : 0);
        #pragma unroll
        for (int r = 0; r < rem % 3; r++)
            pair1(acct[jr2 + r], s1, mxt[i], mxt[jr2 + r], wt[i], wt[jr2 + r]);
        acct[i] += s0 + s1;
    }
}

__global__ __launch_bounds__(128, 4)
void wos_kernel(const float* __restrict__ x,
                const float* __restrict__ mask,
                const float* __restrict__ weight,
                const float* __restrict__ bias,
                float* __restrict__ out)
{
    __shared__ float msk[NCH * DTOT];        // mask per nc
    __shared__ float wgs[NCH * DTOT];        // gated weights: w>tol ? w : 0
    __shared__ float ptile[3][3][PX + 2];    // halo tile for PX pixels
    __shared__ float mxs[128 * DHALF];       // per-thread tile0 mx (stride 27)
    __shared__ float accs[128 * DHALF];      // per-thread tile0 acc

    const int tid = threadIdx.x + threadIdx.y * 16;   // x = nc(16), y = pixel(PX)

    for (int e = tid; e < NCH * DTOT; e += 128) {
        msk[e] = mask[e];
        float w = weight[e];
        wgs[e] = (w > TOL) ? w : 0.0f;
    }

    const int n0  = blockIdx.x * PX;         // PX consecutive pixels, same (b,h)
    const int b   = n0 >> 12;
    const int rem = n0 & 4095;
    const int h   = rem >> 6;
    const int w0  = rem & 63;

    for (int e = tid; e < 3 * 3 * (PX + 2); e += 128) {
        int c   = e / (3 * (PX + 2));
        int r   = (e / (PX + 2)) % 3;
        int col = e % (PX + 2);
        int gr  = h - 1 + r;
        int gc  = w0 - 1 + col;
        float v = 0.0f;
        if ((unsigned)gr < 64u && (unsigned)gc < 64u)
            v = x[((b * 3 + c) * 64 + gr) * 64 + gc];
        ptile[c][r][col] = v;
    }
    __syncthreads();

    const int nc = threadIdx.x;
    const int py = threadIdx.y;
    const int n  = n0 + py;
    const int mb = nc * DTOT;
    const int sb = tid * DHALF;              // this thread's smem slice

    float mxt[DHALF], acct[DHALF], wt[DHALF];

    // ================= Phase A: tile0 (d = 0..26, mx = p + mask) =================
    #pragma unroll
    for (int c = 0; c < 3; c++)
        #pragma unroll
        for (int r = 0; r < 3; r++)
            #pragma unroll
            for (int kw = 0; kw < 3; kw++) {
                int d = c * 9 + r * 3 + kw;
                mxt[d]  = ptile[c][r][py + kw] + msk[mb + d];
                wt[d]   = wgs[mb + d];
                acct[d] = wt[d];             // inclusive: starts at own weight
            }

    triangle27(mxt, acct, wt);

    #pragma unroll
    for (int d = 0; d < DHALF; d++) {        // park tile0 in smem
        mxs[sb + d]  = mxt[d];
        accs[sb + d] = acct[d];
    }

    // ================= Phase B: tile1 (d = 27..53, mx = mask - p) ================
    #pragma unroll
    for (int c = 0; c < 3; c++)
        #pragma unroll
        for (int r = 0; r < 3; r++)
            #pragma unroll
            for (int kw = 0; kw < 3; kw++) {
                int d = c * 9 + r * 3 + kw;
                mxt[d]  = msk[mb + DHALF + d] - ptile[c][r][py + kw];
                wt[d]   = wgs[mb + DHALF + d];
                acct[d] = wt[d];
            }

    triangle27(mxt, acct, wt);

    // cross pairs: global i in tile0 (<27) vs j in tile1 (>=27): always i < j
    #pragma unroll
    for (int i = 0; i < DHALF; i++) {
        float mi = mxs[sb + i];
        float wi = wgs[mb + i];
        float s0 = 0.0f, s1 = 0.0f;
        #pragma unroll
        for (int k = 0; k < 4; k++) {
            const int j = k * 6;
            pair6(acct[j], acct[j+1], acct[j+2], acct[j+3], acct[j+4], acct[j+5],
                  s0, s1, mi,
                  mxt[j], mxt[j+1], mxt[j+2], mxt[j+3], mxt[j+4], mxt[j+5],
                  wi,
                  wt[j], wt[j+1], wt[j+2], wt[j+3], wt[j+4], wt[j+5]);
        }
        pair3(acct[24], acct[25], acct[26], s0, mi,
              mxt[24], mxt[25], mxt[26], wi, wt[24], wt[25], wt[26]);
        accs[sb + i] += s0 + s1;             // per-thread RMW, no races
    }

    // ================= selection epilogue =================
    const float biasv = bias[nc];
    float selMin = FLT_MAX;
    float fbMax  = -FLT_MAX;
    int found = 0, anynz = 0;

    #pragma unroll
    for (int j = 0; j < DHALF; j++) {        // tile0 from smem
        float wjv = wgs[mb + j];
        if (wjv > 0.0f) {
            anynz = 1;
            float vj = mxs[sb + j];
            fbMax = fmaxf(fbMax, vj);
            if (accs[sb + j] <= biasv) { found = 1; selMin = fminf(selMin, vj); }
        }
    }
    #pragma unroll
    for (int j = 0; j < DHALF; j++) {        // tile1 from regs
        if (wt[j] > 0.0f) {
            anynz = 1;
            float vj = mxt[j];
            fbMax = fmaxf(fbMax, vj);
            if (acct[j] <= biasv) { found = 1; selMin = fminf(selMin, vj); }
        }
    }

    float res = found ? selMin : (anynz ? fbMax : 0.0f);
    out[n * NCH + nc] = res;                 // flat layout: coalesced per warp
}

extern "C" void kernel_launch(void* const* d_in, const int* in_sizes, int n_in,
                              void* d_out, int out_size) {
    const float* x      = (const float*)d_in[0];
    const float* mask   = (const float*)d_in[1];
    const float* weight = (const float*)d_in[2];
    const float* bias   = (const float*)d_in[3];
    float* out = (float*)d_out;

    // 32768 pixels / 8 per block = 4096 blocks; block = 16 nc x 8 pixels
    wos_kernel<<<4096, dim3(16, PX)>>>(x, mask, weight, bias, out);
}